// round 10
// baseline (speedup 1.0000x reference)
#include <cuda_runtime.h>
#include <cuda_fp16.h>

#define H     4096
#define K     32
#define WO    4065
#define HP2   2048            // half2 (uint) pitch of scratch rows
#define COUT  65              // output rows per pass-2 chunk (1 + 2*32)

// fp16 scratch: 4096 rows x 2048 half2 = 33.5 MB (kept L2-resident)
__device__ unsigned g_tmp[(size_t)H * HP2];

__device__ __forceinline__ int sk(int x) { return x + (x >> 4); }   // lane stride 17
__device__ __forceinline__ int hs(int i) { return i + (i >> 3); }   // stride-9 skew

__device__ __forceinline__ float4 ldcs4(const float4* p) {
    float4 r;
    asm volatile("ld.global.cs.v4.f32 {%0,%1,%2,%3}, [%4];"
                 : "=f"(r.x), "=f"(r.y), "=f"(r.z), "=f"(r.w) : "l"(p));
    return r;
}
__device__ __forceinline__ void stcs(float* p, float v) {
    asm volatile("st.global.cs.f32 [%0], %1;" :: "l"(p), "f"(v));
}
__device__ __forceinline__ float2 uph2(unsigned u) {
    return __half22float2(*(const __half2*)&u);
}

// ---------------------------------------------------------------------------
// Pass 1: dist = (img - som)^2/(var+eps), horizontal 32-wide box sum, fp16
// scratch. .cs loads keep L2 free so the scratch stays resident for pass 2.
// ---------------------------------------------------------------------------
__global__ void __launch_bounds__(256, 8)
row_pass(const float* __restrict__ img,
         const float* __restrict__ som,
         const float* __restrict__ var)
{
    __shared__ float d[4352];
    __shared__ float irow[32];

    const int y = blockIdx.x;
    const int t = threadIdx.x;

    if (t < 32) irow[t] = img[((y & 31) << 5) + t];
    __syncthreads();

    const float4* s4 = (const float4*)(som + (size_t)y * H);
    const float4* v4 = (const float4*)(var + (size_t)y * H);
    const float4  iv = ((const float4*)irow)[t & 7];

#pragma unroll
    for (int k = 0; k < 4; k++) {
        int i4 = t + (k << 8);
        float4 s = ldcs4(s4 + i4);
        float4 v = ldcs4(v4 + i4);
        int x = i4 << 2;
        float f0 = iv.x - s.x, f1 = iv.y - s.y, f2 = iv.z - s.z, f3 = iv.w - s.w;
        d[sk(x)]     = __fdividef(f0 * f0, v.x + 1e-8f);
        d[sk(x + 1)] = __fdividef(f1 * f1, v.y + 1e-8f);
        d[sk(x + 2)] = __fdividef(f2 * f2, v.z + 1e-8f);
        d[sk(x + 3)] = __fdividef(f3 * f3, v.w + 1e-8f);
    }
    __syncthreads();

    const int base = t << 4;
    const int jmax = (base < WO) ? min(16, WO - base) : 0;
    float res[16];
#pragma unroll
    for (int j = 0; j < 16; j++) res[j] = 0.f;

    if (jmax > 0) {
        float s = 0.f;
#pragma unroll
        for (int i = 0; i < K; i++) s += d[sk(base + i)];
        res[0] = s;
#pragma unroll
        for (int j = 1; j < 16; j++) {
            s += d[sk(base + j + K - 1)] - d[sk(base + j - 1)];
            if (j < jmax) res[j] = s;
        }
    }
    __syncthreads();

    unsigned* hbuf = (unsigned*)d;
#pragma unroll
    for (int p = 0; p < 8; p++) {
        __half2 h = __floats2half2_rn(res[2 * p], res[2 * p + 1]);
        hbuf[hs((t << 3) + p)] = *(unsigned*)&h;
    }
    __syncthreads();

    unsigned* grow = g_tmp + (size_t)y * HP2;
#pragma unroll
    for (int k = 0; k < 8; k++) {
        int idx = t + (k << 8);
        if (idx < 2033) grow[idx] = hbuf[hs(idx)];
    }
}

// ---------------------------------------------------------------------------
// Pass 2: vertical 32-wide running box sum. Register ping-pong ring holds the
// last 32 half2 values -> ONE scratch load per row (trailing subtract comes
// from registers). MLP=32/thread, 1 LDG + 2 STG per 2 outputs.
// ---------------------------------------------------------------------------
__global__ void __launch_bounds__(256)
col_pass(float* __restrict__ out)
{
    const int c2 = blockIdx.x * 256 + threadIdx.x;
    if (c2 >= 2033) return;
    const int x0 = c2 << 1;
    const bool x1ok = (x0 + 1) < WO;

    const int j0 = blockIdx.y * COUT;          // 63 chunks, j0 <= 4030
    const unsigned* col = g_tmp + c2;

    unsigned a[32], b[32];

    // warmup: rows j0 .. j0+31 (j0+31 <= 4061, always valid)
#pragma unroll
    for (int i = 0; i < 32; i++)
        a[i] = col[(size_t)(j0 + i) * HP2];
    float s0 = 0.f, s1 = 0.f;
#pragma unroll
    for (int i = 0; i < 32; i++) {
        float2 v = uph2(a[i]);
        s0 += v.x; s1 += v.y;
    }
    {
        float* o = out + (size_t)j0 * WO + x0;
        stcs(o, s0);
        if (x1ok) stcs(o + 1, s1);
    }

    // batch 1: new rows j0+32 .. j0+63 -> outputs j0+1 .. j0+32
#pragma unroll
    for (int i = 0; i < 32; i++) {
        int r = min(j0 + 32 + i, H - 1);       // clamp; clamped rows never output
        b[i] = col[(size_t)r * HP2];
    }
#pragma unroll
    for (int i = 0; i < 32; i++) {
        float2 n = uph2(b[i]), o2 = uph2(a[i]);
        s0 += n.x - o2.x;
        s1 += n.y - o2.y;
        int j = j0 + 1 + i;
        if (j < WO) {
            float* o = out + (size_t)j * WO + x0;
            stcs(o, s0);
            if (x1ok) stcs(o + 1, s1);
        }
    }

    // batch 2: new rows j0+64 .. j0+95 -> outputs j0+33 .. j0+64
#pragma unroll
    for (int i = 0; i < 32; i++) {
        int r = min(j0 + 64 + i, H - 1);
        a[i] = col[(size_t)r * HP2];
    }
#pragma unroll
    for (int i = 0; i < 32; i++) {
        float2 n = uph2(a[i]), o2 = uph2(b[i]);
        s0 += n.x - o2.x;
        s1 += n.y - o2.y;
        int j = j0 + 33 + i;
        if (j < WO) {
            float* o = out + (size_t)j * WO + x0;
            stcs(o, s0);
            if (x1ok) stcs(o + 1, s1);
        }
    }
}

// ---------------------------------------------------------------------------
extern "C" void kernel_launch(void* const* d_in, const int* in_sizes, int n_in,
                              void* d_out, int out_size)
{
    const float* img = (const float*)d_in[0];   // [32,32]
    const float* som = (const float*)d_in[1];   // [4096,4096]
    const float* var = (const float*)d_in[2];   // [4096,4096]
    float*       out = (float*)d_out;           // [4065,4065]

    row_pass<<<H, 256>>>(img, som, var);

    dim3 grid2((2033 + 255) / 256,              // 8
               (WO + COUT - 1) / COUT);         // 63 -> 504 CTAs
    col_pass<<<grid2, 256>>>(out);
}